// round 13
// baseline (speedup 1.0000x reference)
#include <cuda_runtime.h>
#include <math.h>
#include <stdint.h>

#define Nn 8192
#define Ff 256

// Scratch (device globals — no allocation allowed)
__device__ float g_Wh[(size_t)Nn * Ff];   // row-major [node][feat], tf32-rounded (L2-resident)
__device__ float g_Wh1[Nn];
__device__ float g_Wh2[Nn];

__device__ __forceinline__ uint32_t f2tf32(float x) {
    uint32_t u; asm("cvt.rna.tf32.f32 %0, %1;" : "=r"(u) : "f"(x)); return u;
}

// D += A*B, tf32 m16n8k8
__device__ __forceinline__ void mma8(float* d, const uint32_t* a, const uint32_t* b) {
    asm volatile(
        "mma.sync.aligned.m16n8k8.row.col.f32.tf32.tf32.f32 "
        "{%0,%1,%2,%3}, {%4,%5,%6,%7}, {%8,%9}, {%0,%1,%2,%3};"
        : "+f"(d[0]), "+f"(d[1]), "+f"(d[2]), "+f"(d[3])
        : "r"(a[0]), "r"(a[1]), "r"(a[2]), "r"(a[3]), "r"(b[0]), "r"(b[1]));
}

__device__ __forceinline__ void cpasync16(uint32_t saddr, const void* gptr) {
    asm volatile("cp.async.cg.shared.global [%0], [%1], 16;" :: "r"(saddr), "l"(gptr));
}

// ---------------------------------------------------------------------------
// Kernel A: Wh = h @ W (fp32 accum) -> g_Wh tf32-rounded; Wh1/Wh2 full prec.
// ---------------------------------------------------------------------------
__global__ __launch_bounds__(256, 1)
void wh_kernel(const float* __restrict__ h, const float* __restrict__ Wm,
               const float* __restrict__ av) {
    __shared__ float h_s[64][36];
    __shared__ float w_s[32 * 256];

    const int tid = threadIdx.x;
    const int rg = tid >> 4, cg = tid & 15;
    const int row0 = blockIdx.x * 64;

    float acc[4][16];
#pragma unroll
    for (int r = 0; r < 4; ++r)
#pragma unroll
        for (int c = 0; c < 16; ++c) acc[r][c] = 0.f;

    for (int k0 = 0; k0 < Ff; k0 += 32) {
        __syncthreads();
        {
            int r = tid >> 2, s = tid & 3;
            const float* src = &h[(size_t)(row0 + r) * Ff + k0 + s * 8];
            float4 v0 = *(const float4*)(src);
            float4 v1 = *(const float4*)(src + 4);
            *(float4*)&h_s[r][s * 8] = v0;
            *(float4*)&h_s[r][s * 8 + 4] = v1;
        }
        {
            const float4* src = (const float4*)&Wm[(size_t)k0 * Ff];
            float4* dst = (float4*)w_s;
#pragma unroll
            for (int i = 0; i < 8; ++i) dst[tid + 256 * i] = src[tid + 256 * i];
        }
        __syncthreads();

#pragma unroll 4
        for (int k = 0; k < 32; ++k) {
            float4 wv[4];
#pragma unroll
            for (int q = 0; q < 4; ++q)
                wv[q] = *(const float4*)&w_s[k * 256 + q * 64 + cg * 4];
#pragma unroll
            for (int r = 0; r < 4; ++r) {
                float hv = h_s[rg * 4 + r][k];
#pragma unroll
                for (int q = 0; q < 4; ++q) {
                    acc[r][q * 4 + 0] += hv * wv[q].x;
                    acc[r][q * 4 + 1] += hv * wv[q].y;
                    acc[r][q * 4 + 2] += hv * wv[q].z;
                    acc[r][q * 4 + 3] += hv * wv[q].w;
                }
            }
        }
    }

#pragma unroll
    for (int r = 0; r < 4; ++r) {
        int row = row0 + rg * 4 + r;
        float s1 = 0.f, s2 = 0.f;
#pragma unroll
        for (int q = 0; q < 4; ++q) {
            int col = q * 64 + cg * 4;
            float4 v;
            v.x = __uint_as_float(f2tf32(acc[r][q * 4 + 0]));
            v.y = __uint_as_float(f2tf32(acc[r][q * 4 + 1]));
            v.z = __uint_as_float(f2tf32(acc[r][q * 4 + 2]));
            v.w = __uint_as_float(f2tf32(acc[r][q * 4 + 3]));
            *(float4*)&g_Wh[(size_t)row * Ff + col] = v;
#pragma unroll
            for (int cc = 0; cc < 4; ++cc) {
                float u = acc[r][q * 4 + cc];
                s1 += u * av[col + cc];
                s2 += u * av[Ff + col + cc];
            }
        }
#pragma unroll
        for (int off = 8; off > 0; off >>= 1) {
            s1 += __shfl_down_sync(0xffffffffu, s1, off, 16);
            s2 += __shfl_down_sync(0xffffffffu, s2, off, 16);
        }
        if (cg == 0) { g_Wh1[row] = s1; g_Wh2[row] = s2; }
    }
}

// ---------------------------------------------------------------------------
// Kernel B: fused masked softmax + tf32 mma.sync GEMM + ELU.
// Grid (128, 2): CTA = 64 rows x 128 feat cols, 256 thr, 8 warps (2m x 4n),
// warp tile 32x32. 2 CTAs/SM. cp.async double-buffered B, 1 sync/tile.
// ---------------------------------------------------------------------------
#define BSTR 136                       // B row stride (floats): 136 % 32 == 8
#define PSTR 36
#define WH_BUF (32 * BSTR)             // 4352 floats / buffer
#define OFF_P  (2 * WH_BUF)            // 8704
#define P_BUF  (64 * PSTR)             // 2304
#define OFF_L  (OFF_P + 2 * P_BUF)     // 13312
#define OFF_RED (OFF_L + 64)           // 13376
#define SMEM_FLOATS (OFF_RED + 256)    // 13632
#define SMEM_BYTES (SMEM_FLOATS * 4)   // 54528

__global__ __launch_bounds__(256, 2)
void gat_mma_kernel(const float* __restrict__ adj, float* __restrict__ out) {
    extern __shared__ float smem[];
    float*    wh_s = smem;
    uint32_t* p_s  = (uint32_t*)(smem + OFF_P);
    float*    l_s  = smem + OFF_L;
    float*    red  = smem + OFF_RED;
    const uint32_t wh_u32 = (uint32_t)__cvta_generic_to_shared(wh_s);

    const int tid = threadIdx.x;
    const int wid = tid >> 5, lane = tid & 31;
    const int g = lane >> 2, tg = lane & 3;
    const int warp_m = wid >> 2, warp_n = wid & 3;
    const int row0 = blockIdx.x * 64;
    const int col0 = blockIdx.y * 128;

    // ---- global max of Wh2 ----
    float mx = -3.0e38f;
    for (int k = tid; k < Nn; k += 256) mx = fmaxf(mx, g_Wh2[k]);
    red[tid] = mx;
    __syncthreads();
    for (int s = 128; s > 0; s >>= 1) {
        if (tid < s) red[tid] = fmaxf(red[tid], red[tid + s]);
        __syncthreads();
    }
    const float Mg = red[0];

    const int prow = tid >> 2, q = tid & 3;      // softmax map: 4 lanes/row, 8 j each
    const float wh1 = g_Wh1[row0 + prow];
    float tmx = wh1 + Mg;
    const float mi = (tmx > 0.f) ? tmx : 0.2f * tmx;   // fixed row shift (>= row max)
    const float* adjrow = adj + (size_t)(row0 + prow) * Nn + q * 8;

    float acc[2][4][4];
#pragma unroll
    for (int m2 = 0; m2 < 2; ++m2)
#pragma unroll
        for (int n = 0; n < 4; ++n)
#pragma unroll
            for (int c = 0; c < 4; ++c) acc[m2][n][c] = 0.f;
    float lsum = 0.f;

    // ---- prologue: cp.async B(0) -> buf0; prefetch adj/Wh2 tile 0 ----
    {
        const float* src = g_Wh + col0;
#pragma unroll
        for (int i = 0; i < 4; ++i) {
            int c = tid + 256 * i;
            int r = c >> 5, c16 = c & 31;
            cpasync16(wh_u32 + (uint32_t)(r * BSTR + c16 * 4) * 4,
                      src + (size_t)r * Ff + c16 * 4);
        }
        asm volatile("cp.async.commit_group;" ::: "memory");
    }
    float4 A0 = *(const float4*)(adjrow);
    float4 A1 = *(const float4*)(adjrow + 4);
    float4 W20 = *(const float4*)(g_Wh2 + q * 8);
    float4 W21 = *(const float4*)(g_Wh2 + q * 8 + 4);

    const int NT = Nn / 32;   // 256 tiles
    for (int t = 0; t < NT; ++t) {
        const int b = t & 1;

        // ---- compute P(t) -> p_s[b] ----
        {
            float av8[8] = {A0.x, A0.y, A0.z, A0.w, A1.x, A1.y, A1.z, A1.w};
            float wv8[8] = {W20.x, W20.y, W20.z, W20.w, W21.x, W21.y, W21.z, W21.w};
            uint32_t pb[8];
#pragma unroll
            for (int k = 0; k < 8; ++k) {
                float e = wh1 + wv8[k];
                float lr = (e > 0.f) ? e : 0.2f * e;
                float p = __expf(lr - mi);
                p = (av8[k] > 0.f) ? p : 0.f;
                uint32_t u = f2tf32(p);
                lsum += __uint_as_float(u);
                pb[k] = u;
            }
            uint32_t* dst = p_s + b * P_BUF + prow * PSTR + q * 8;
            *(uint4*)(dst)     = make_uint4(pb[0], pb[1], pb[2], pb[3]);
            *(uint4*)(dst + 4) = make_uint4(pb[4], pb[5], pb[6], pb[7]);
        }
        // prefetch next tile's adj / Wh2 into regs (hidden under MMA phase)
        if (t + 1 < NT) {
            A0 = *(const float4*)(adjrow + (t + 1) * 32);
            A1 = *(const float4*)(adjrow + (t + 1) * 32 + 4);
            W20 = *(const float4*)(g_Wh2 + (t + 1) * 32 + q * 8);
            W21 = *(const float4*)(g_Wh2 + (t + 1) * 32 + q * 8 + 4);
        }
        asm volatile("cp.async.wait_group 0;" ::: "memory");
        __syncthreads();   // B(t) + P(t) visible; everyone done reading buf b

        // issue cp.async for B(t+1) into the other buffer (overlaps MMA below)
        if (t + 1 < NT) {
            const float* src = g_Wh + (size_t)((t + 1) * 32) * Ff + col0;
            const uint32_t dstb = wh_u32 + (uint32_t)((b ^ 1) * WH_BUF) * 4;
#pragma unroll
            for (int i = 0; i < 4; ++i) {
                int c = tid + 256 * i;
                int r = c >> 5, c16 = c & 31;
                cpasync16(dstb + (uint32_t)(r * BSTR + c16 * 4) * 4,
                          src + (size_t)r * Ff + c16 * 4);
            }
            asm volatile("cp.async.commit_group;" ::: "memory");
        }

        // ---- MMA phase: warp tile 32x32, K=32 ----
        const uint32_t* pbuf = p_s + b * P_BUF;
        const uint32_t* bb = (const uint32_t*)(wh_s + b * WH_BUF);
#pragma unroll
        for (int k8 = 0; k8 < 4; ++k8) {
            uint32_t a[2][4];
#pragma unroll
            for (int m2 = 0; m2 < 2; ++m2) {
                int ar = warp_m * 32 + m2 * 16 + g;
                int ac = k8 * 8 + tg;
                a[m2][0] = pbuf[ar * PSTR + ac];
                a[m2][1] = pbuf[(ar + 8) * PSTR + ac];
                a[m2][2] = pbuf[ar * PSTR + ac + 4];
                a[m2][3] = pbuf[(ar + 8) * PSTR + ac + 4];
            }
#pragma unroll
            for (int n = 0; n < 4; ++n) {
                uint32_t bv[2];
                int bc = warp_n * 32 + n * 8 + g;
                bv[0] = bb[(k8 * 8 + tg) * BSTR + bc];
                bv[1] = bb[(k8 * 8 + tg + 4) * BSTR + bc];
                mma8(acc[0][n], a[0], bv);
                mma8(acc[1][n], a[1], bv);
            }
        }
    }

    // ---- row sums ----
    lsum += __shfl_xor_sync(0xffffffffu, lsum, 1);
    lsum += __shfl_xor_sync(0xffffffffu, lsum, 2);
    if (q == 0) l_s[prow] = lsum;
    __syncthreads();

    // ---- epilogue: normalize, ELU, store ----
#pragma unroll
    for (int m2 = 0; m2 < 2; ++m2) {
        int rl0 = warp_m * 32 + m2 * 16 + g;
        int rl1 = rl0 + 8;
        float inv0 = 1.0f / l_s[rl0];
        float inv1 = 1.0f / l_s[rl1];
        float* o0 = out + (size_t)(row0 + rl0) * Ff + col0;
        float* o1 = out + (size_t)(row0 + rl1) * Ff + col0;
#pragma unroll
        for (int n = 0; n < 4; ++n) {
            int col = warp_n * 32 + n * 8 + 2 * tg;
            float2 v0, v1;
            v0.x = acc[m2][n][0] * inv0;  v0.y = acc[m2][n][1] * inv0;
            v1.x = acc[m2][n][2] * inv1;  v1.y = acc[m2][n][3] * inv1;
            v0.x = (v0.x > 0.f) ? v0.x : expm1f(v0.x);
            v0.y = (v0.y > 0.f) ? v0.y : expm1f(v0.y);
            v1.x = (v1.x > 0.f) ? v1.x : expm1f(v1.x);
            v1.y = (v1.y > 0.f) ? v1.y : expm1f(v1.y);
            *(float2*)&o0[col] = v0;
            *(float2*)&o1[col] = v1;
        }
    }
}

// ---------------------------------------------------------------------------
extern "C" void kernel_launch(void* const* d_in, const int* in_sizes, int n_in,
                              void* d_out, int out_size) {
    const float *h = nullptr, *adj = nullptr, *Wm = nullptr, *av = nullptr;
    for (int i = 0; i < n_in; ++i) {
        long sz = (long)in_sizes[i];
        if      (sz == (long)Nn * Nn) adj = (const float*)d_in[i];
        else if (sz == (long)Nn * Ff) h   = (const float*)d_in[i];
        else if (sz == (long)Ff * Ff) Wm  = (const float*)d_in[i];
        else if (sz == 2L * Ff)       av  = (const float*)d_in[i];
    }
    (void)out_size;
    static int configured = 0;
    if (!configured) {
        cudaFuncSetAttribute(gat_mma_kernel,
                             cudaFuncAttributeMaxDynamicSharedMemorySize, SMEM_BYTES);
        configured = 1;
    }
    wh_kernel<<<Nn / 64, 256>>>(h, Wm, av);
    gat_mma_kernel<<<dim3(Nn / 64, 2), 256, SMEM_BYTES>>>(adj, (float*)d_out);
}

// round 14
// speedup vs baseline: 1.0027x; 1.0027x over previous
#include <cuda_runtime.h>
#include <math.h>
#include <stdint.h>

#define Nn 8192
#define Ff 256

// Scratch (device globals — no allocation allowed)
__device__ float g_Wh[(size_t)Nn * Ff];   // row-major [node][feat], tf32-rounded (L2-resident)
__device__ float g_Wh1[Nn];
__device__ float g_Wh2[Nn];

__device__ __forceinline__ uint32_t f2tf32(float x) {
    uint32_t u; asm("cvt.rna.tf32.f32 %0, %1;" : "=r"(u) : "f"(x)); return u;
}

// D += A*B, tf32 m16n8k8
__device__ __forceinline__ void mma8(float* d, const uint32_t* a, const uint32_t* b) {
    asm volatile(
        "mma.sync.aligned.m16n8k8.row.col.f32.tf32.tf32.f32 "
        "{%0,%1,%2,%3}, {%4,%5,%6,%7}, {%8,%9}, {%0,%1,%2,%3};"
        : "+f"(d[0]), "+f"(d[1]), "+f"(d[2]), "+f"(d[3])
        : "r"(a[0]), "r"(a[1]), "r"(a[2]), "r"(a[3]), "r"(b[0]), "r"(b[1]));
}

__device__ __forceinline__ void cpasync16(uint32_t saddr, const void* gptr) {
    asm volatile("cp.async.cg.shared.global [%0], [%1], 16;" :: "r"(saddr), "l"(gptr));
}

// ---------------------------------------------------------------------------
// Kernel A: Wh = h @ W (fp32 accum) -> g_Wh tf32-rounded; Wh1/Wh2 full prec.
// ---------------------------------------------------------------------------
__global__ __launch_bounds__(256, 1)
void wh_kernel(const float* __restrict__ h, const float* __restrict__ Wm,
               const float* __restrict__ av) {
    __shared__ float h_s[64][36];
    __shared__ float w_s[32 * 256];

    const int tid = threadIdx.x;
    const int rg = tid >> 4, cg = tid & 15;
    const int row0 = blockIdx.x * 64;

    float acc[4][16];
#pragma unroll
    for (int r = 0; r < 4; ++r)
#pragma unroll
        for (int c = 0; c < 16; ++c) acc[r][c] = 0.f;

    for (int k0 = 0; k0 < Ff; k0 += 32) {
        __syncthreads();
        {
            int r = tid >> 2, s = tid & 3;
            const float* src = &h[(size_t)(row0 + r) * Ff + k0 + s * 8];
            float4 v0 = *(const float4*)(src);
            float4 v1 = *(const float4*)(src + 4);
            *(float4*)&h_s[r][s * 8] = v0;
            *(float4*)&h_s[r][s * 8 + 4] = v1;
        }
        {
            const float4* src = (const float4*)&Wm[(size_t)k0 * Ff];
            float4* dst = (float4*)w_s;
#pragma unroll
            for (int i = 0; i < 8; ++i) dst[tid + 256 * i] = src[tid + 256 * i];
        }
        __syncthreads();

#pragma unroll 4
        for (int k = 0; k < 32; ++k) {
            float4 wv[4];
#pragma unroll
            for (int q = 0; q < 4; ++q)
                wv[q] = *(const float4*)&w_s[k * 256 + q * 64 + cg * 4];
#pragma unroll
            for (int r = 0; r < 4; ++r) {
                float hv = h_s[rg * 4 + r][k];
#pragma unroll
                for (int q = 0; q < 4; ++q) {
                    acc[r][q * 4 + 0] += hv * wv[q].x;
                    acc[r][q * 4 + 1] += hv * wv[q].y;
                    acc[r][q * 4 + 2] += hv * wv[q].z;
                    acc[r][q * 4 + 3] += hv * wv[q].w;
                }
            }
        }
    }

#pragma unroll
    for (int r = 0; r < 4; ++r) {
        int row = row0 + rg * 4 + r;
        float s1 = 0.f, s2 = 0.f;
#pragma unroll
        for (int q = 0; q < 4; ++q) {
            int col = q * 64 + cg * 4;
            float4 v;
            v.x = __uint_as_float(f2tf32(acc[r][q * 4 + 0]));
            v.y = __uint_as_float(f2tf32(acc[r][q * 4 + 1]));
            v.z = __uint_as_float(f2tf32(acc[r][q * 4 + 2]));
            v.w = __uint_as_float(f2tf32(acc[r][q * 4 + 3]));
            *(float4*)&g_Wh[(size_t)row * Ff + col] = v;
#pragma unroll
            for (int cc = 0; cc < 4; ++cc) {
                float u = acc[r][q * 4 + cc];
                s1 += u * av[col + cc];
                s2 += u * av[Ff + col + cc];
            }
        }
#pragma unroll
        for (int off = 8; off > 0; off >>= 1) {
            s1 += __shfl_down_sync(0xffffffffu, s1, off, 16);
            s2 += __shfl_down_sync(0xffffffffu, s2, off, 16);
        }
        if (cg == 0) { g_Wh1[row] = s1; g_Wh2[row] = s2; }
    }
}

// ---------------------------------------------------------------------------
// Kernel B: fused masked softmax + tf32 mma.sync GEMM + ELU.
// Grid (128, 2): CTA = 64 rows x 128 feat cols, 256 thr, 8 warps (2m x 4n),
// warp tile 32x32. 2 CTAs/SM. cp.async double-buffered B, 1 sync/tile.
// ---------------------------------------------------------------------------
#define BSTR 136                       // B row stride (floats): 136 % 32 == 8
#define PSTR 36
#define WH_BUF (32 * BSTR)             // 4352 floats / buffer
#define OFF_P  (2 * WH_BUF)            // 8704
#define P_BUF  (64 * PSTR)             // 2304
#define OFF_L  (OFF_P + 2 * P_BUF)     // 13312
#define OFF_RED (OFF_L + 64)           // 13376
#define SMEM_FLOATS (OFF_RED + 256)    // 13632
#define SMEM_BYTES (SMEM_FLOATS * 4)   // 54528

__global__ __launch_bounds__(256, 2)
void gat_mma_kernel(const float* __restrict__ adj, float* __restrict__ out) {
    extern __shared__ float smem[];
    float*    wh_s = smem;
    uint32_t* p_s  = (uint32_t*)(smem + OFF_P);
    float*    l_s  = smem + OFF_L;
    float*    red  = smem + OFF_RED;
    const uint32_t wh_u32 = (uint32_t)__cvta_generic_to_shared(wh_s);

    const int tid = threadIdx.x;
    const int wid = tid >> 5, lane = tid & 31;
    const int g = lane >> 2, tg = lane & 3;
    const int warp_m = wid >> 2, warp_n = wid & 3;
    const int row0 = blockIdx.x * 64;
    const int col0 = blockIdx.y * 128;

    // ---- global max of Wh2 ----
    float mx = -3.0e38f;
    for (int k = tid; k < Nn; k += 256) mx = fmaxf(mx, g_Wh2[k]);
    red[tid] = mx;
    __syncthreads();
    for (int s = 128; s > 0; s >>= 1) {
        if (tid < s) red[tid] = fmaxf(red[tid], red[tid + s]);
        __syncthreads();
    }
    const float Mg = red[0];

    const int prow = tid >> 2, q = tid & 3;      // softmax map: 4 lanes/row, 8 j each
    const float wh1 = g_Wh1[row0 + prow];
    float tmx = wh1 + Mg;
    const float mi = (tmx > 0.f) ? tmx : 0.2f * tmx;   // fixed row shift (>= row max)
    const float* adjrow = adj + (size_t)(row0 + prow) * Nn + q * 8;

    float acc[2][4][4];
#pragma unroll
    for (int m2 = 0; m2 < 2; ++m2)
#pragma unroll
        for (int n = 0; n < 4; ++n)
#pragma unroll
            for (int c = 0; c < 4; ++c) acc[m2][n][c] = 0.f;
    float lsum = 0.f;

    // ---- prologue: cp.async B(0) -> buf0; prefetch adj/Wh2 tile 0 ----
    {
        const float* src = g_Wh + col0;
#pragma unroll
        for (int i = 0; i < 4; ++i) {
            int c = tid + 256 * i;
            int r = c >> 5, c16 = c & 31;
            cpasync16(wh_u32 + (uint32_t)(r * BSTR + c16 * 4) * 4,
                      src + (size_t)r * Ff + c16 * 4);
        }
        asm volatile("cp.async.commit_group;" ::: "memory");
    }
    float4 A0 = *(const float4*)(adjrow);
    float4 A1 = *(const float4*)(adjrow + 4);
    float4 W20 = *(const float4*)(g_Wh2 + q * 8);
    float4 W21 = *(const float4*)(g_Wh2 + q * 8 + 4);

    const int NT = Nn / 32;   // 256 tiles
    for (int t = 0; t < NT; ++t) {
        const int b = t & 1;

        // ---- compute P(t) -> p_s[b] ----
        {
            float av8[8] = {A0.x, A0.y, A0.z, A0.w, A1.x, A1.y, A1.z, A1.w};
            float wv8[8] = {W20.x, W20.y, W20.z, W20.w, W21.x, W21.y, W21.z, W21.w};
            uint32_t pb[8];
#pragma unroll
            for (int k = 0; k < 8; ++k) {
                float e = wh1 + wv8[k];
                float lr = (e > 0.f) ? e : 0.2f * e;
                float p = __expf(lr - mi);
                p = (av8[k] > 0.f) ? p : 0.f;
                uint32_t u = f2tf32(p);
                lsum += __uint_as_float(u);
                pb[k] = u;
            }
            uint32_t* dst = p_s + b * P_BUF + prow * PSTR + q * 8;
            *(uint4*)(dst)     = make_uint4(pb[0], pb[1], pb[2], pb[3]);
            *(uint4*)(dst + 4) = make_uint4(pb[4], pb[5], pb[6], pb[7]);
        }
        // prefetch next tile's adj / Wh2 into regs (hidden under MMA phase)
        if (t + 1 < NT) {
            A0 = *(const float4*)(adjrow + (t + 1) * 32);
            A1 = *(const float4*)(adjrow + (t + 1) * 32 + 4);
            W20 = *(const float4*)(g_Wh2 + (t + 1) * 32 + q * 8);
            W21 = *(const float4*)(g_Wh2 + (t + 1) * 32 + q * 8 + 4);
        }
        asm volatile("cp.async.wait_group 0;" ::: "memory");
        __syncthreads();   // B(t) + P(t) visible; everyone done reading buf b

        // issue cp.async for B(t+1) into the other buffer (overlaps MMA below)
        if (t + 1 < NT) {
            const float* src = g_Wh + (size_t)((t + 1) * 32) * Ff + col0;
            const uint32_t dstb = wh_u32 + (uint32_t)((b ^ 1) * WH_BUF) * 4;
#pragma unroll
            for (int i = 0; i < 4; ++i) {
                int c = tid + 256 * i;
                int r = c >> 5, c16 = c & 31;
                cpasync16(dstb + (uint32_t)(r * BSTR + c16 * 4) * 4,
                          src + (size_t)r * Ff + c16 * 4);
            }
            asm volatile("cp.async.commit_group;" ::: "memory");
        }

        // ---- MMA phase: warp tile 32x32, K=32 ----
        const uint32_t* pbuf = p_s + b * P_BUF;
        const uint32_t* bb = (const uint32_t*)(wh_s + b * WH_BUF);
#pragma unroll
        for (int k8 = 0; k8 < 4; ++k8) {
            uint32_t a[2][4];
#pragma unroll
            for (int m2 = 0; m2 < 2; ++m2) {
                int ar = warp_m * 32 + m2 * 16 + g;
                int ac = k8 * 8 + tg;
                a[m2][0] = pbuf[ar * PSTR + ac];
                a[m2][1] = pbuf[(ar + 8) * PSTR + ac];
                a[m2][2] = pbuf[ar * PSTR + ac + 4];
                a[m2][3] = pbuf[(ar + 8) * PSTR + ac + 4];
            }
#pragma unroll
            for (int n = 0; n < 4; ++n) {
                uint32_t bv[2];
                int bc = warp_n * 32 + n * 8 + g;
                bv[0] = bb[(k8 * 8 + tg) * BSTR + bc];
                bv[1] = bb[(k8 * 8 + tg + 4) * BSTR + bc];
                mma8(acc[0][n], a[0], bv);
                mma8(acc[1][n], a[1], bv);
            }
        }
    }

    // ---- row sums ----
    lsum += __shfl_xor_sync(0xffffffffu, lsum, 1);
    lsum += __shfl_xor_sync(0xffffffffu, lsum, 2);
    if (q == 0) l_s[prow] = lsum;
    __syncthreads();

    // ---- epilogue: normalize, ELU, store ----
#pragma unroll
    for (int m2 = 0; m2 < 2; ++m2) {
        int rl0 = warp_m * 32 + m2 * 16 + g;
        int rl1 = rl0 + 8;
        float inv0 = 1.0f / l_s[rl0];
        float inv1 = 1.0f / l_s[rl1];
        float* o0 = out + (size_t)(row0 + rl0) * Ff + col0;
        float* o1 = out + (size_t)(row0 + rl1) * Ff + col0;
#pragma unroll
        for (int n = 0; n < 4; ++n) {
            int col = warp_n * 32 + n * 8 + 2 * tg;
            float2 v0, v1;
            v0.x = acc[m2][n][0] * inv0;  v0.y = acc[m2][n][1] * inv0;
            v1.x = acc[m2][n][2] * inv1;  v1.y = acc[m2][n][3] * inv1;
            v0.x = (v0.x > 0.f) ? v0.x : expm1f(v0.x);
            v0.y = (v0.y > 0.f) ? v0.y : expm1f(v0.y);
            v1.x = (v1.x > 0.f) ? v1.x : expm1f(v1.x);
            v1.y = (v1.y > 0.f) ? v1.y : expm1f(v1.y);
            *(float2*)&o0[col] = v0;
            *(float2*)&o1[col] = v1;
        }
    }
}

// ---------------------------------------------------------------------------
extern "C" void kernel_launch(void* const* d_in, const int* in_sizes, int n_in,
                              void* d_out, int out_size) {
    const float *h = nullptr, *adj = nullptr, *Wm = nullptr, *av = nullptr;
    for (int i = 0; i < n_in; ++i) {
        long sz = (long)in_sizes[i];
        if      (sz == (long)Nn * Nn) adj = (const float*)d_in[i];
        else if (sz == (long)Nn * Ff) h   = (const float*)d_in[i];
        else if (sz == (long)Ff * Ff) Wm  = (const float*)d_in[i];
        else if (sz == 2L * Ff)       av  = (const float*)d_in[i];
    }
    (void)out_size;
    static int configured = 0;
    if (!configured) {
        cudaFuncSetAttribute(gat_mma_kernel,
                             cudaFuncAttributeMaxDynamicSharedMemorySize, SMEM_BYTES);
        configured = 1;
    }
    wh_kernel<<<Nn / 64, 256>>>(h, Wm, av);
    gat_mma_kernel<<<dim3(Nn / 64, 2), 256, SMEM_BYTES>>>(adj, (float*)d_out);
}

// round 15
// speedup vs baseline: 1.0031x; 1.0003x over previous
#include <cuda_runtime.h>
#include <math.h>
#include <stdint.h>

#define Nn 8192
#define Ff 256

// Scratch (device globals — no allocation allowed)
__device__ float g_Wh[(size_t)Nn * Ff];   // row-major [node][feat], tf32-rounded (L2-resident)
__device__ float g_Wh1[Nn];
__device__ float g_Wh2[Nn];

__device__ __forceinline__ uint32_t f2tf32(float x) {
    uint32_t u; asm("cvt.rna.tf32.f32 %0, %1;" : "=r"(u) : "f"(x)); return u;
}

// D += A*B, tf32 m16n8k8
__device__ __forceinline__ void mma8(float* d, const uint32_t* a, const uint32_t* b) {
    asm volatile(
        "mma.sync.aligned.m16n8k8.row.col.f32.tf32.tf32.f32 "
        "{%0,%1,%2,%3}, {%4,%5,%6,%7}, {%8,%9}, {%0,%1,%2,%3};"
        : "+f"(d[0]), "+f"(d[1]), "+f"(d[2]), "+f"(d[3])
        : "r"(a[0]), "r"(a[1]), "r"(a[2]), "r"(a[3]), "r"(b[0]), "r"(b[1]));
}

__device__ __forceinline__ void cpasync16(uint32_t saddr, const void* gptr) {
    asm volatile("cp.async.cg.shared.global [%0], [%1], 16;" :: "r"(saddr), "l"(gptr));
}

// ---------------------------------------------------------------------------
// Kernel A: Wh = h @ W (fp32 accum) -> g_Wh tf32-rounded; Wh1/Wh2 full prec.
// ---------------------------------------------------------------------------
__global__ __launch_bounds__(256, 1)
void wh_kernel(const float* __restrict__ h, const float* __restrict__ Wm,
               const float* __restrict__ av) {
    __shared__ float h_s[64][36];
    __shared__ float w_s[32 * 256];

    const int tid = threadIdx.x;
    const int rg = tid >> 4, cg = tid & 15;
    const int row0 = blockIdx.x * 64;

    float acc[4][16];
#pragma unroll
    for (int r = 0; r < 4; ++r)
#pragma unroll
        for (int c = 0; c < 16; ++c) acc[r][c] = 0.f;

    for (int k0 = 0; k0 < Ff; k0 += 32) {
        __syncthreads();
        {
            int r = tid >> 2, s = tid & 3;
            const float* src = &h[(size_t)(row0 + r) * Ff + k0 + s * 8];
            float4 v0 = *(const float4*)(src);
            float4 v1 = *(const float4*)(src + 4);
            *(float4*)&h_s[r][s * 8] = v0;
            *(float4*)&h_s[r][s * 8 + 4] = v1;
        }
        {
            const float4* src = (const float4*)&Wm[(size_t)k0 * Ff];
            float4* dst = (float4*)w_s;
#pragma unroll
            for (int i = 0; i < 8; ++i) dst[tid + 256 * i] = src[tid + 256 * i];
        }
        __syncthreads();

#pragma unroll 4
        for (int k = 0; k < 32; ++k) {
            float4 wv[4];
#pragma unroll
            for (int q = 0; q < 4; ++q)
                wv[q] = *(const float4*)&w_s[k * 256 + q * 64 + cg * 4];
#pragma unroll
            for (int r = 0; r < 4; ++r) {
                float hv = h_s[rg * 4 + r][k];
#pragma unroll
                for (int q = 0; q < 4; ++q) {
                    acc[r][q * 4 + 0] += hv * wv[q].x;
                    acc[r][q * 4 + 1] += hv * wv[q].y;
                    acc[r][q * 4 + 2] += hv * wv[q].z;
                    acc[r][q * 4 + 3] += hv * wv[q].w;
                }
            }
        }
    }

#pragma unroll
    for (int r = 0; r < 4; ++r) {
        int row = row0 + rg * 4 + r;
        float s1 = 0.f, s2 = 0.f;
#pragma unroll
        for (int q = 0; q < 4; ++q) {
            int col = q * 64 + cg * 4;
            float4 v;
            v.x = __uint_as_float(f2tf32(acc[r][q * 4 + 0]));
            v.y = __uint_as_float(f2tf32(acc[r][q * 4 + 1]));
            v.z = __uint_as_float(f2tf32(acc[r][q * 4 + 2]));
            v.w = __uint_as_float(f2tf32(acc[r][q * 4 + 3]));
            *(float4*)&g_Wh[(size_t)row * Ff + col] = v;
#pragma unroll
            for (int cc = 0; cc < 4; ++cc) {
                float u = acc[r][q * 4 + cc];
                s1 += u * av[col + cc];
                s2 += u * av[Ff + col + cc];
            }
        }
#pragma unroll
        for (int off = 8; off > 0; off >>= 1) {
            s1 += __shfl_down_sync(0xffffffffu, s1, off, 16);
            s2 += __shfl_down_sync(0xffffffffu, s2, off, 16);
        }
        if (cg == 0) { g_Wh1[row] = s1; g_Wh2[row] = s2; }
    }
}

// ---------------------------------------------------------------------------
// Kernel B: fused masked softmax + tf32 mma.sync GEMM + ELU.
// Grid (128, 2): CTA = 64 rows x 128 feat cols, 256 thr, 8 warps (2m x 4n),
// warp tile 32x32. 2 CTAs/SM. cp.async double-buffered B, 1 sync/tile.
// ---------------------------------------------------------------------------
#define BSTR 136                       // B row stride (floats): 136 % 32 == 8
#define PSTR 36
#define WH_BUF (32 * BSTR)             // 4352 floats / buffer
#define OFF_P  (2 * WH_BUF)            // 8704
#define P_BUF  (64 * PSTR)             // 2304
#define OFF_L  (OFF_P + 2 * P_BUF)     // 13312
#define OFF_RED (OFF_L + 64)           // 13376
#define SMEM_FLOATS (OFF_RED + 256)    // 13632
#define SMEM_BYTES (SMEM_FLOATS * 4)   // 54528

__global__ __launch_bounds__(256, 2)
void gat_mma_kernel(const float* __restrict__ adj, float* __restrict__ out) {
    extern __shared__ float smem[];
    float*    wh_s = smem;
    uint32_t* p_s  = (uint32_t*)(smem + OFF_P);
    float*    l_s  = smem + OFF_L;
    float*    red  = smem + OFF_RED;
    const uint32_t wh_u32 = (uint32_t)__cvta_generic_to_shared(wh_s);

    const int tid = threadIdx.x;
    const int wid = tid >> 5, lane = tid & 31;
    const int g = lane >> 2, tg = lane & 3;
    const int warp_m = wid >> 2, warp_n = wid & 3;
    const int row0 = blockIdx.x * 64;
    const int col0 = blockIdx.y * 128;

    // ---- global max of Wh2 ----
    float mx = -3.0e38f;
    for (int k = tid; k < Nn; k += 256) mx = fmaxf(mx, g_Wh2[k]);
    red[tid] = mx;
    __syncthreads();
    for (int s = 128; s > 0; s >>= 1) {
        if (tid < s) red[tid] = fmaxf(red[tid], red[tid + s]);
        __syncthreads();
    }
    const float Mg = red[0];

    const int prow = tid >> 2, q = tid & 3;      // softmax map: 4 lanes/row, 8 j each
    const float wh1 = g_Wh1[row0 + prow];
    float tmx = wh1 + Mg;
    const float mi = (tmx > 0.f) ? tmx : 0.2f * tmx;   // fixed row shift (>= row max)
    const float* adjrow = adj + (size_t)(row0 + prow) * Nn + q * 8;

    float acc[2][4][4];
#pragma unroll
    for (int m2 = 0; m2 < 2; ++m2)
#pragma unroll
        for (int n = 0; n < 4; ++n)
#pragma unroll
            for (int c = 0; c < 4; ++c) acc[m2][n][c] = 0.f;
    float lsum = 0.f;

    // ---- prologue: cp.async B(0) -> buf0; prefetch adj/Wh2 tile 0 ----
    {
        const float* src = g_Wh + col0;
#pragma unroll
        for (int i = 0; i < 4; ++i) {
            int c = tid + 256 * i;
            int r = c >> 5, c16 = c & 31;
            cpasync16(wh_u32 + (uint32_t)(r * BSTR + c16 * 4) * 4,
                      src + (size_t)r * Ff + c16 * 4);
        }
        asm volatile("cp.async.commit_group;" ::: "memory");
    }
    float4 A0 = *(const float4*)(adjrow);
    float4 A1 = *(const float4*)(adjrow + 4);
    float4 W20 = *(const float4*)(g_Wh2 + q * 8);
    float4 W21 = *(const float4*)(g_Wh2 + q * 8 + 4);

    const int NT = Nn / 32;   // 256 tiles
    for (int t = 0; t < NT; ++t) {
        const int b = t & 1;

        // ---- compute P(t) -> p_s[b] ----
        {
            float av8[8] = {A0.x, A0.y, A0.z, A0.w, A1.x, A1.y, A1.z, A1.w};
            float wv8[8] = {W20.x, W20.y, W20.z, W20.w, W21.x, W21.y, W21.z, W21.w};
            uint32_t pb[8];
#pragma unroll
            for (int k = 0; k < 8; ++k) {
                float e = wh1 + wv8[k];
                float lr = (e > 0.f) ? e : 0.2f * e;
                float p = __expf(lr - mi);
                p = (av8[k] > 0.f) ? p : 0.f;
                uint32_t u = f2tf32(p);
                lsum += __uint_as_float(u);
                pb[k] = u;
            }
            uint32_t* dst = p_s + b * P_BUF + prow * PSTR + q * 8;
            *(uint4*)(dst)     = make_uint4(pb[0], pb[1], pb[2], pb[3]);
            *(uint4*)(dst + 4) = make_uint4(pb[4], pb[5], pb[6], pb[7]);
        }
        // prefetch next tile's adj / Wh2 into regs (hidden under MMA phase)
        if (t + 1 < NT) {
            A0 = *(const float4*)(adjrow + (t + 1) * 32);
            A1 = *(const float4*)(adjrow + (t + 1) * 32 + 4);
            W20 = *(const float4*)(g_Wh2 + (t + 1) * 32 + q * 8);
            W21 = *(const float4*)(g_Wh2 + (t + 1) * 32 + q * 8 + 4);
        }
        asm volatile("cp.async.wait_group 0;" ::: "memory");
        __syncthreads();   // B(t) + P(t) visible; everyone done reading buf b

        // issue cp.async for B(t+1) into the other buffer (overlaps MMA below)
        if (t + 1 < NT) {
            const float* src = g_Wh + (size_t)((t + 1) * 32) * Ff + col0;
            const uint32_t dstb = wh_u32 + (uint32_t)((b ^ 1) * WH_BUF) * 4;
#pragma unroll
            for (int i = 0; i < 4; ++i) {
                int c = tid + 256 * i;
                int r = c >> 5, c16 = c & 31;
                cpasync16(dstb + (uint32_t)(r * BSTR + c16 * 4) * 4,
                          src + (size_t)r * Ff + c16 * 4);
            }
            asm volatile("cp.async.commit_group;" ::: "memory");
        }

        // ---- MMA phase: warp tile 32x32, K=32 ----
        const uint32_t* pbuf = p_s + b * P_BUF;
        const uint32_t* bb = (const uint32_t*)(wh_s + b * WH_BUF);
#pragma unroll
        for (int k8 = 0; k8 < 4; ++k8) {
            uint32_t a[2][4];
#pragma unroll
            for (int m2 = 0; m2 < 2; ++m2) {
                int ar = warp_m * 32 + m2 * 16 + g;
                int ac = k8 * 8 + tg;
                a[m2][0] = pbuf[ar * PSTR + ac];
                a[m2][1] = pbuf[(ar + 8) * PSTR + ac];
                a[m2][2] = pbuf[ar * PSTR + ac + 4];
                a[m2][3] = pbuf[(ar + 8) * PSTR + ac + 4];
            }
#pragma unroll
            for (int n = 0; n < 4; ++n) {
                uint32_t bv[2];
                int bc = warp_n * 32 + n * 8 + g;
                bv[0] = bb[(k8 * 8 + tg) * BSTR + bc];
                bv[1] = bb[(k8 * 8 + tg + 4) * BSTR + bc];
                mma8(acc[0][n], a[0], bv);
                mma8(acc[1][n], a[1], bv);
            }
        }
    }

    // ---- row sums ----
    lsum += __shfl_xor_sync(0xffffffffu, lsum, 1);
    lsum += __shfl_xor_sync(0xffffffffu, lsum, 2);
    if (q == 0) l_s[prow] = lsum;
    __syncthreads();

    // ---- epilogue: normalize, ELU, store ----
#pragma unroll
    for (int m2 = 0; m2 < 2; ++m2) {
        int rl0 = warp_m * 32 + m2 * 16 + g;
        int rl1 = rl0 + 8;
        float inv0 = 1.0f / l_s[rl0];
        float inv1 = 1.0f / l_s[rl1];
        float* o0 = out + (size_t)(row0 + rl0) * Ff + col0;
        float* o1 = out + (size_t)(row0 + rl1) * Ff + col0;
#pragma unroll
        for (int n = 0; n < 4; ++n) {
            int col = warp_n * 32 + n * 8 + 2 * tg;
            float2 v0, v1;
            v0.x = acc[m2][n][0] * inv0;  v0.y = acc[m2][n][1] * inv0;
            v1.x = acc[m2][n][2] * inv1;  v1.y = acc[m2][n][3] * inv1;
            v0.x = (v0.x > 0.f) ? v0.x : expm1f(v0.x);
            v0.y = (v0.y > 0.f) ? v0.y : expm1f(v0.y);
            v1.x = (v1.x > 0.f) ? v1.x : expm1f(v1.x);
            v1.y = (v1.y > 0.f) ? v1.y : expm1f(v1.y);
            *(float2*)&o0[col] = v0;
            *(float2*)&o1[col] = v1;
        }
    }
}

// ---------------------------------------------------------------------------
extern "C" void kernel_launch(void* const* d_in, const int* in_sizes, int n_in,
                              void* d_out, int out_size) {
    const float *h = nullptr, *adj = nullptr, *Wm = nullptr, *av = nullptr;
    for (int i = 0; i < n_in; ++i) {
        long sz = (long)in_sizes[i];
        if      (sz == (long)Nn * Nn) adj = (const float*)d_in[i];
        else if (sz == (long)Nn * Ff) h   = (const float*)d_in[i];
        else if (sz == (long)Ff * Ff) Wm  = (const float*)d_in[i];
        else if (sz == 2L * Ff)       av  = (const float*)d_in[i];
    }
    (void)out_size;
    static int configured = 0;
    if (!configured) {
        cudaFuncSetAttribute(gat_mma_kernel,
                             cudaFuncAttributeMaxDynamicSharedMemorySize, SMEM_BYTES);
        configured = 1;
    }
    wh_kernel<<<Nn / 64, 256>>>(h, Wm, av);
    gat_mma_kernel<<<dim3(Nn / 64, 2), 256, SMEM_BYTES>>>(adj, (float*)d_out);
}

// round 16
// speedup vs baseline: 1.3248x; 1.3207x over previous
#include <cuda_runtime.h>
#include <math.h>
#include <stdint.h>

#define Nn 8192
#define Ff 256
#define LOG2E 1.4426950408889634f

// Scratch (device globals — no allocation allowed)
__device__ float g_Wh[(size_t)Nn * Ff];   // row-major [node][feat], tf32-rounded (L2-resident)
__device__ float g_Wh1[Nn];
__device__ float g_Wh2[Nn];              // pre-scaled by LOG2E

__device__ __forceinline__ uint32_t f2tf32(float x) {
    uint32_t u; asm("cvt.rna.tf32.f32 %0, %1;" : "=r"(u) : "f"(x)); return u;
}
__device__ __forceinline__ float ex2f(float x) {
    float y; asm("ex2.approx.f32 %0, %1;" : "=f"(y) : "f"(x)); return y;
}
__device__ __forceinline__ float4 lds128(uint32_t a) {
    float4 v;
    asm volatile("ld.shared.v4.f32 {%0,%1,%2,%3}, [%4];"
                 : "=f"(v.x), "=f"(v.y), "=f"(v.z), "=f"(v.w) : "r"(a));
    return v;
}

// D += A*B, tf32 m16n8k8
__device__ __forceinline__ void mma8(float* d, const uint32_t* a, const uint32_t* b) {
    asm volatile(
        "mma.sync.aligned.m16n8k8.row.col.f32.tf32.tf32.f32 "
        "{%0,%1,%2,%3}, {%4,%5,%6,%7}, {%8,%9}, {%0,%1,%2,%3};"
        : "+f"(d[0]), "+f"(d[1]), "+f"(d[2]), "+f"(d[3])
        : "r"(a[0]), "r"(a[1]), "r"(a[2]), "r"(a[3]), "r"(b[0]), "r"(b[1]));
}

__device__ __forceinline__ void cpasync16(uint32_t saddr, const void* gptr) {
    asm volatile("cp.async.cg.shared.global [%0], [%1], 16;" :: "r"(saddr), "l"(gptr));
}

// ---------------------------------------------------------------------------
// Kernel A: Wh = h @ W (fp32 accum) -> g_Wh tf32-rounded; Wh1 raw; Wh2*LOG2E.
// ---------------------------------------------------------------------------
__global__ __launch_bounds__(256, 1)
void wh_kernel(const float* __restrict__ h, const float* __restrict__ Wm,
               const float* __restrict__ av) {
    __shared__ float h_s[64][36];
    __shared__ float w_s[32 * 256];

    const int tid = threadIdx.x;
    const int rg = tid >> 4, cg = tid & 15;
    const int row0 = blockIdx.x * 64;

    float acc[4][16];
#pragma unroll
    for (int r = 0; r < 4; ++r)
#pragma unroll
        for (int c = 0; c < 16; ++c) acc[r][c] = 0.f;

    for (int k0 = 0; k0 < Ff; k0 += 32) {
        __syncthreads();
        {
            int r = tid >> 2, s = tid & 3;
            const float* src = &h[(size_t)(row0 + r) * Ff + k0 + s * 8];
            float4 v0 = *(const float4*)(src);
            float4 v1 = *(const float4*)(src + 4);
            *(float4*)&h_s[r][s * 8] = v0;
            *(float4*)&h_s[r][s * 8 + 4] = v1;
        }
        {
            const float4* src = (const float4*)&Wm[(size_t)k0 * Ff];
            float4* dst = (float4*)w_s;
#pragma unroll
            for (int i = 0; i < 8; ++i) dst[tid + 256 * i] = src[tid + 256 * i];
        }
        __syncthreads();

#pragma unroll 4
        for (int k = 0; k < 32; ++k) {
            float4 wv[4];
#pragma unroll
            for (int q = 0; q < 4; ++q)
                wv[q] = *(const float4*)&w_s[k * 256 + q * 64 + cg * 4];
#pragma unroll
            for (int r = 0; r < 4; ++r) {
                float hv = h_s[rg * 4 + r][k];
#pragma unroll
                for (int q = 0; q < 4; ++q) {
                    acc[r][q * 4 + 0] += hv * wv[q].x;
                    acc[r][q * 4 + 1] += hv * wv[q].y;
                    acc[r][q * 4 + 2] += hv * wv[q].z;
                    acc[r][q * 4 + 3] += hv * wv[q].w;
                }
            }
        }
    }

#pragma unroll
    for (int r = 0; r < 4; ++r) {
        int row = row0 + rg * 4 + r;
        float s1 = 0.f, s2 = 0.f;
#pragma unroll
        for (int q = 0; q < 4; ++q) {
            int col = q * 64 + cg * 4;
            float4 v;
            v.x = __uint_as_float(f2tf32(acc[r][q * 4 + 0]));
            v.y = __uint_as_float(f2tf32(acc[r][q * 4 + 1]));
            v.z = __uint_as_float(f2tf32(acc[r][q * 4 + 2]));
            v.w = __uint_as_float(f2tf32(acc[r][q * 4 + 3]));
            *(float4*)&g_Wh[(size_t)row * Ff + col] = v;
#pragma unroll
            for (int cc = 0; cc < 4; ++cc) {
                float u = acc[r][q * 4 + cc];
                s1 += u * av[col + cc];
                s2 += u * av[Ff + col + cc];
            }
        }
#pragma unroll
        for (int off = 8; off > 0; off >>= 1) {
            s1 += __shfl_down_sync(0xffffffffu, s1, off, 16);
            s2 += __shfl_down_sync(0xffffffffu, s2, off, 16);
        }
        if (cg == 0) { g_Wh1[row] = s1; g_Wh2[row] = s2 * LOG2E; }
    }
}

// ---------------------------------------------------------------------------
// Kernel B: fused masked softmax (log2 domain) + tf32 mma.sync GEMM + ELU.
// Grid (128, 2): CTA = 64 rows x 128 cols, 8 warps (2m x 4n), 2 CTAs/SM.
// 3-deep cp.async ring for B and adj (issued 2 tiles ahead), 1 sync/tile.
// ---------------------------------------------------------------------------
#define BSTR 136                       // B row stride (floats): 136 % 32 == 8
#define PSTR 36
#define WH_BUF (32 * BSTR)             // 4352 floats
#define OFF_P   (3 * WH_BUF)           // 13056
#define P_BUF   (64 * PSTR)            // 2304
#define OFF_ADJ (OFF_P + 2 * P_BUF)    // 17664
#define ADJ_BUF 2048                   // 64 rows x 32 j, thread-order
#define OFF_L   (OFF_ADJ + 3 * ADJ_BUF)  // 23808
#define OFF_RED (OFF_L + 64)             // 23872
#define SMEM_FLOATS (OFF_RED + 256)      // 24128
#define SMEM_BYTES  (SMEM_FLOATS * 4)    // 96512

__global__ __launch_bounds__(256, 2)
void gat_mma_kernel(const float* __restrict__ adj, float* __restrict__ out) {
    extern __shared__ float smem[];
    const uint32_t sb = (uint32_t)__cvta_generic_to_shared(smem);
    float* l_s = smem + OFF_L;
    float* red = smem + OFF_RED;
    uint32_t* p_s = (uint32_t*)(smem + OFF_P);

    const int tid = threadIdx.x;
    const int wid = tid >> 5, lane = tid & 31;
    const int g = lane >> 2, tg = lane & 3;
    const int warp_m = wid >> 2, warp_n = wid & 3;
    const int row0 = blockIdx.x * 64;
    const int col0 = blockIdx.y * 128;

    // ---- global max of (Wh2 * LOG2E) ----
    float mx = -3.0e38f;
    for (int k = tid; k < Nn; k += 256) mx = fmaxf(mx, g_Wh2[k]);
    red[tid] = mx;
    __syncthreads();
    for (int s = 128; s > 0; s >>= 1) {
        if (tid < s) red[tid] = fmaxf(red[tid], red[tid + s]);
        __syncthreads();
    }
    const float MgL = red[0];

    const int prow = tid >> 2, q = tid & 3;
    const float wh1 = g_Wh1[row0 + prow];
    const float Mg = MgL * (1.0f / LOG2E);
    float tmx = wh1 + Mg;
    const float mi = (tmx > 0.f) ? tmx : 0.2f * tmx;   // fixed row shift (>= row max)
    const float miL = mi * LOG2E;
    const float wh1L = wh1 * LOG2E;
    const float c1 = wh1L - miL;                       // (e - mi)*L      = c1 + w2L
    const float c0 = 0.2f * wh1L - miL;                // (0.2e - mi)*L   = fma(.2, w2L, c0)

    // ---- persistent cp.async pointers (incremented per tile, no IMAD churn) ----
    const float* bsrc[4];
    uint32_t bdst[4];
#pragma unroll
    for (int i = 0; i < 4; ++i) {
        int idx = tid + 256 * i, r = idx >> 5, c16 = idx & 31;
        bsrc[i] = g_Wh + col0 + (size_t)r * Ff + c16 * 4;
        bdst[i] = (uint32_t)(r * BSTR + c16 * 4) * 4u;
    }
    const float* asrc = adj + (size_t)(row0 + prow) * Nn + q * 8;   // next tile to fetch
    const uint32_t adst = (uint32_t)tid * 32u;
    const float* w2p = g_Wh2 + q * 8;

    float acc[2][4][4];
#pragma unroll
    for (int m2 = 0; m2 < 2; ++m2)
#pragma unroll
        for (int n = 0; n < 4; ++n)
#pragma unroll
            for (int c = 0; c < 4; ++c) acc[m2][n][c] = 0.f;
    float lsum = 0.f;

    // ---- prologue: issue groups for tiles 0 and 1; load W2(0) regs ----
#pragma unroll
    for (int pre = 0; pre < 2; ++pre) {
        uint32_t wdst = sb + (uint32_t)(pre * WH_BUF) * 4u;
#pragma unroll
        for (int i = 0; i < 4; ++i) { cpasync16(wdst + bdst[i], bsrc[i]); bsrc[i] += 32 * Ff; }
        uint32_t ad = sb + (uint32_t)(OFF_ADJ + pre * ADJ_BUF) * 4u + adst;
        cpasync16(ad, asrc); cpasync16(ad + 16, asrc + 4);
        asrc += 32;
        asm volatile("cp.async.commit_group;" ::: "memory");
    }
    float4 W20 = *(const float4*)(w2p);
    float4 W21 = *(const float4*)(w2p + 4);
    w2p += 32;

    const int NT = Nn / 32;   // 256 tiles
    int b3 = 0, bn = 2;       // consume buffer, issue buffer (mod-3 ring)
    for (int t = 0; t < NT; ++t) {
        const int b2 = t & 1;
        // G(t) must be complete; G(t+1) may still fly
        asm volatile("cp.async.wait_group 1;" ::: "memory");

        // ---- softmax(t): adj from own smem slots, w2 from regs ----
        {
            uint32_t aaddr = sb + (uint32_t)(OFF_ADJ + b3 * ADJ_BUF) * 4u + adst;
            float4 A0 = lds128(aaddr);
            float4 A1 = lds128(aaddr + 16);
            float av8[8] = {A0.x, A0.y, A0.z, A0.w, A1.x, A1.y, A1.z, A1.w};
            float wv8[8] = {W20.x, W20.y, W20.z, W20.w, W21.x, W21.y, W21.z, W21.w};
            // prefetch W2(t+1) regs (L1/L2-hot)
            if (t + 1 < NT) {
                W20 = *(const float4*)(w2p);
                W21 = *(const float4*)(w2p + 4);
                w2p += 32;
            }
            uint32_t pb[8];
#pragma unroll
            for (int k = 0; k < 8; ++k) {
                float t1 = c1 + wv8[k];
                float t0 = fmaf(0.2f, wv8[k], c0);
                float x = fmaxf(t1, t0);
                float p = ex2f(x) * av8[k];           // adj ∈ {0,1} masks exactly
                uint32_t u = f2tf32(p);
                lsum += __uint_as_float(u);
                pb[k] = u;
            }
            uint32_t* dst = p_s + b2 * P_BUF + prow * PSTR + q * 8;
            *(uint4*)(dst)     = make_uint4(pb[0], pb[1], pb[2], pb[3]);
            *(uint4*)(dst + 4) = make_uint4(pb[4], pb[5], pb[6], pb[7]);
        }
        __syncthreads();   // P(t) visible; B(t) cross-thread visible; MMA(t-1) drained

        // ---- issue G(t+2) into ring slot bn ----
        if (t + 2 < NT) {
            uint32_t wdst = sb + (uint32_t)(bn * WH_BUF) * 4u;
#pragma unroll
            for (int i = 0; i < 4; ++i) { cpasync16(wdst + bdst[i], bsrc[i]); bsrc[i] += 32 * Ff; }
            uint32_t ad = sb + (uint32_t)(OFF_ADJ + bn * ADJ_BUF) * 4u + adst;
            cpasync16(ad, asrc); cpasync16(ad + 16, asrc + 4);
            asrc += 32;
        }
        asm volatile("cp.async.commit_group;" ::: "memory");  // empty groups keep FIFO exact

        // ---- MMA(t): warp tile 32x32, K=32 ----
        const uint32_t* pbuf = p_s + b2 * P_BUF;
        const uint32_t* bb = (const uint32_t*)(smem + b3 * WH_BUF);
#pragma unroll
        for (int k8 = 0; k8 < 4; ++k8) {
            uint32_t a[2][4];
#pragma unroll
            for (int m2 = 0; m2 < 2; ++m2) {
                int ar = warp_m * 32 + m2 * 16 + g;
                int ac = k8 * 8 + tg;
                a[m2][0] = pbuf[ar * PSTR + ac];
                a[m2][1] = pbuf[(ar + 8) * PSTR + ac];
                a[m2][2] = pbuf[ar * PSTR + ac + 4];
                a[m2][3] = pbuf[(ar + 8) * PSTR + ac + 4];
            }
#pragma unroll
            for (int n = 0; n < 4; ++n) {
                uint32_t bv[2];
                int bc = warp_n * 32 + n * 8 + g;
                bv[0] = bb[(k8 * 8 + tg) * BSTR + bc];
                bv[1] = bb[(k8 * 8 + tg + 4) * BSTR + bc];
                mma8(acc[0][n], a[0], bv);
                mma8(acc[1][n], a[1], bv);
            }
        }

        // rotate ring indices
        b3 = (b3 == 2) ? 0 : b3 + 1;
        bn = (bn == 2) ? 0 : bn + 1;
    }

    // ---- row sums ----
    lsum += __shfl_xor_sync(0xffffffffu, lsum, 1);
    lsum += __shfl_xor_sync(0xffffffffu, lsum, 2);
    if (q == 0) l_s[prow] = lsum;
    __syncthreads();

    // ---- epilogue: normalize, ELU, store ----
#pragma unroll
    for (int m2 = 0; m2 < 2; ++m2) {
        int rl0 = warp_m * 32 + m2 * 16 + g;
        int rl1 = rl0 + 8;
        float inv0 = 1.0f / l_s[rl0];
        float inv1 = 1.0f / l_s[rl1];
        float* o0 = out + (size_t)(row0 + rl0) * Ff + col0;
        float* o1 = out + (size_t)(row0 + rl1) * Ff + col0;
#pragma unroll
        for (int n = 0; n < 4; ++n) {
            int col = warp_n * 32 + n * 8 + 2 * tg;
            float2 v0, v1;
            v0.x = acc[m2][n][0] * inv0;  v0.y = acc[m2][n][1] * inv0;
            v1.x = acc[m2][n][2] * inv1;  v1.y = acc[m2][n][3] * inv1;
            v0.x = (v0.x > 0.f) ? v0.x : expm1f(v0.x);
            v0.y = (v0.y > 0.f) ? v0.y : expm1f(v0.y);
            v1.x = (v1.x > 0.f) ? v1.x : expm1f(v1.x);
            v1.y = (v1.y > 0.f) ? v1.y : expm1f(v1.y);
            *(float2*)&o0[col] = v0;
            *(float2*)&o1[col] = v1;
        }
    }
}

// ---------------------------------------------------------------------------
extern "C" void kernel_launch(void* const* d_in, const int* in_sizes, int n_in,
                              void* d_out, int out_size) {
    const float *h = nullptr, *adj = nullptr, *Wm = nullptr, *av = nullptr;
    for (int i = 0; i < n_in; ++i) {
        long sz = (long)in_sizes[i];
        if      (sz == (long)Nn * Nn) adj = (const float*)d_in[i];
        else if (sz == (long)Nn * Ff) h   = (const float*)d_in[i];
        else if (sz == (long)Ff * Ff) Wm  = (const float*)d_in[i];
        else if (sz == 2L * Ff)       av  = (const float*)d_in[i];
    }
    (void)out_size;
    static int configured = 0;
    if (!configured) {
        cudaFuncSetAttribute(gat_mma_kernel,
                             cudaFuncAttributeMaxDynamicSharedMemorySize, SMEM_BYTES);
        configured = 1;
    }
    wh_kernel<<<Nn / 64, 256>>>(h, Wm, av);
    gat_mma_kernel<<<dim3(Nn / 64, 2), 256, SMEM_BYTES>>>(adj, (float*)d_out);
}